// round 15
// baseline (speedup 1.0000x reference)
#include <cuda_runtime.h>

#define RR 16384
#define SS 64
#define GG 128
#define EE 16
#define NPTS (RR*SS)
#define SX (GG*GG*EE)
#define SY (GG*EE)
#define TPB 128
#define PPT 2            // points per thread (A = s0-31, B = s32-63 of the SAME ray)

typedef unsigned long long u64;

// ---- scratch (per-point) ----
__device__ float4 g_srgb[NPTS];   // (sigma, r, g, b)
__device__ float4 g_nrm[NPTS];    // (nx, ny, nz, 0)

// Large streaming matrices in the constant bank (uniform-port loads).
// cW2T and cW3 are PRESCALED by 0.01 in k_prep (activation 100x-scale algebra).
__constant__ __align__(16) float cW2T[4096];   // [k][j] = 0.01*sw2[j][k]
__constant__ __align__(16) float cCW2T[4096];  // [k][j] = cw2[j][k]   (unscaled)
__constant__ __align__(16) float cW3[1024];    // 0.01 * (16x64 row-major)
__constant__ __align__(16) float cCW3[192];    // 3x64 row-major       (unscaled)

// ---- packed f32x2 helpers ----
__device__ __forceinline__ u64 pk2(float a, float b){
  u64 r; asm("mov.b64 %0, {%1,%2};" : "=l"(r) : "f"(a), "f"(b)); return r;
}
__device__ __forceinline__ float2 upk2(u64 v){
  float2 t; asm("mov.b64 {%0,%1}, %2;" : "=f"(t.x), "=f"(t.y) : "l"(v)); return t;
}
__device__ __forceinline__ u64 ffma2(u64 a, u64 b, u64 c){
  u64 r; asm("fma.rn.f32x2 %0, %1, %2, %3;" : "=l"(r) : "l"(a), "l"(b), "l"(c)); return r;
}
__device__ __forceinline__ u64 fmul2(u64 a, u64 b){
  u64 r; asm("mul.rn.f32x2 %0, %1, %2;" : "=l"(r) : "l"(a), "l"(b)); return r;
}

__device__ __forceinline__ float decode_scalar(const unsigned* p){
  unsigned u = *p;
  if (u == 0u) return 0.0f;
  if ((u >> 23) == 0u) return (float)(int)u;   // small integer bit pattern
  return __uint_as_float(u);
}
// softplus(100 z)  (NOT divided by 100 — downstream weights are prescaled)
__device__ __forceinline__ float softplus_raw(float z){
  float y = 100.0f*z;
  float t = __expf(-fabsf(y));
  return fmaxf(y,0.0f) + __logf(1.0f + t);
}
// sigmoid(100 z) from h' = softplus(100 z)
__device__ __forceinline__ float dact1(float h){ return 1.0f - __expf(-h); }

// ---- shared layout (float offsets; dynamic smem) ----
#define OFF_W1    0      // 1024  (64x16 row-major)
#define OFF_B1    1024   // 64
#define OFF_B2    1088   // 64
#define OFF_B3    1152   // 16
#define OFF_CW1P  1168   // 1536  (64x24, rows zero-padded from 18)
#define OFF_CB1   2704   // 64
#define OFF_CB2   2768   // 64
#define OFF_CB3   2832   // 3
#define OFF_S1    2840   // 64*TPB u64 per-thread scratch (16B aligned)
#define SM_FLOATS (OFF_S1 + 64*TPB*2)
#define SMEM_BYTES (SM_FLOATS*4)

struct Geo {
  float fx, fy, fz;
  int base;
  bool ax, ay, az;
};

// ---- prep: transposed / raw weights into the constant bank (with prescale) ----
__global__ void k_prep(const float* __restrict__ sw2, const float* __restrict__ cw2,
                       const float* __restrict__ sw3, const float* __restrict__ cw3,
                       float* __restrict__ dW2T, float* __restrict__ dCW2T,
                       float* __restrict__ dW3, float* __restrict__ dCW3)
{
  for (int i = threadIdx.x; i < 4096; i += blockDim.x){
    int j = i >> 6, k = i & 63;
    dW2T [k*64 + j] = 0.01f * sw2[i];
    dCW2T[k*64 + j] = cw2[i];
  }
  for (int i = threadIdx.x; i < 1024; i += blockDim.x) dW3[i] = 0.01f * sw3[i];
  for (int i = threadIdx.x; i < 192;  i += blockDim.x) dCW3[i] = cw3[i];
}

// ---- single-point color MLP (used when the partner point is fully masked) ----
__device__ __forceinline__ void color_single(const float* sm, const u64* ci,
                                             u64* acc /*32*/, float* rgb)
{
  #pragma unroll
  for (int j = 0; j < 32; ++j) acc[j] = ((const u64*)(sm + OFF_CB2))[j];

  #pragma unroll 1
  for (int j = 0; j < 64; ++j){
    const ulonglong2* w = (const ulonglong2*)(sm + OFF_CW1P + j*24);
    ulonglong2 wa=w[0], wb=w[1], wc=w[2], wd=w[3];
    u64 w8 = ((const u64*)(sm + OFF_CW1P + j*24))[8];
    const float bias = sm[OFF_CB1+j];
    u64 z0=0ull, z1=0ull;
    z0=ffma2(wa.x,ci[0],z0); z1=ffma2(wa.y,ci[1],z1);
    z0=ffma2(wb.x,ci[2],z0); z1=ffma2(wb.y,ci[3],z1);
    z0=ffma2(wc.x,ci[4],z0); z1=ffma2(wc.y,ci[5],z1);
    z0=ffma2(wd.x,ci[6],z0); z1=ffma2(wd.y,ci[7],z1);
    z0=ffma2(w8,  ci[8],z0);
    float2 t0=upk2(z0), t1=upk2(z1);
    float z = bias + ((t0.x+t1.x)+(t0.y+t1.y));
    float c1 = fmaxf(z, 0.0f);
    const u64 cp = pk2(c1,c1);
    const ulonglong2* wt = (const ulonglong2*)(cCW2T + j*64);
    #pragma unroll
    for (int q = 0; q < 16; ++q){
      ulonglong2 wv = wt[q];
      acc[2*q]   = ffma2(wv.x, cp, acc[2*q]);
      acc[2*q+1] = ffma2(wv.y, cp, acc[2*q+1]);
    }
  }
  #pragma unroll
  for (int j = 0; j < 32; ++j){
    float2 t = upk2(acc[j]); acc[j] = pk2(fmaxf(t.x,0.0f), fmaxf(t.y,0.0f));
  }
  #pragma unroll 1
  for (int c = 0; c < 3; ++c){
    const ulonglong2* w = (const ulonglong2*)(cCW3 + c*64);
    u64 a0=0ull, a1=0ull;
    #pragma unroll
    for (int q = 0; q < 16; ++q){
      ulonglong2 wv = w[q];
      a0 = ffma2(wv.x, acc[2*q],   a0);
      a1 = ffma2(wv.y, acc[2*q+1], a1);
    }
    float bias = sm[OFF_CB3+c];
    float2 t0=upk2(a0), t1=upk2(a1);
    rgb[c] = 1.0f / (1.0f + __expf(-(bias + ((t0.x+t1.x)+(t0.y+t1.y)))));
  }
}

__global__ void __launch_bounds__(TPB, 2)
k_points(const float* __restrict__ rays_o, const float* __restrict__ rays_d,
         const float* __restrict__ grid,
         const float* __restrict__ sw1, const float* __restrict__ sb1,
         const float* __restrict__ sb2, const float* __restrict__ sb3,
         const float* __restrict__ cw1, const float* __restrict__ cb1,
         const float* __restrict__ cb2, const float* __restrict__ cb3,
         const float* __restrict__ beta_p,
         const unsigned* __restrict__ near_p, const unsigned* __restrict__ far_p,
         float* __restrict__ out_grads)
{
  extern __shared__ __align__(16) float sm[];
  const int tid = threadIdx.x;

  // ---- cooperative staging of SMALL arrays ----
  for (int i = tid; i < 1024; i += TPB) sm[OFF_W1+i]=sw1[i];
  for (int i = tid; i < 1536; i += TPB) sm[OFF_CW1P+i] = 0.0f;
  if (tid < 64){ sm[OFF_B1+tid]=sb1[tid]; sm[OFF_B2+tid]=sb2[tid];
                 sm[OFF_CB1+tid]=cb1[tid]; sm[OFF_CB2+tid]=cb2[tid]; }
  if (tid < 16) sm[OFF_B3+tid]=sb3[tid];
  if (tid < 3)  sm[OFF_CB3+tid]=cb3[tid];
  __syncthreads();
  for (int i = tid; i < 1152; i += TPB){
    int j = i / 18, c = i - j*18;
    sm[OFF_CW1P + j*24 + c] = cw1[i];
  }
  __syncthreads();

  u64* s1p = ((u64*)(sm + OFF_S1)) + tid;   // per-thread scratch, stride TPB per k

  // warp = one ray; lane l: A = sample l, B = sample l+32
  const int wid  = tid >> 5;
  const int lane = tid & 31;
  const int ray  = blockIdx.x*4 + wid;
  const int pA = ray*64 + lane;
  const int pB = pA + 32;

  const float nearf = decode_scalar(near_p);
  const float farf  = decode_scalar(far_p);
  const float span  = farf - nearf;

  // ---- geometry + forward gather (packed embeddings: 8 pairs per point) ----
  Geo gA, gB;
  u64 epA[8], epB[8];

  #pragma unroll
  for (int pi = 0; pi < PPT; ++pi){
    const int p = pi ? pB : pA;
    const int s = p & 63;
    const float tm = nearf + span * ((s + 0.5f) * (1.0f/64.0f));
    const float px = fmaf(tm, rays_d[3*ray+0], rays_o[3*ray+0]);
    const float py = fmaf(tm, rays_d[3*ray+1], rays_o[3*ray+1]);
    const float pz = fmaf(tm, rays_d[3*ray+2], rays_o[3*ray+2]);

    const float HALF = 0.5f*(float)(GG-1);
    float grx = (px*(1.0f/1.3f) + 1.0f)*HALF;
    float gry = (py*(1.0f/1.3f) + 1.0f)*HALF;
    float grz = (pz*(1.0f/1.3f) + 1.0f)*HALF;
    const float GM1 = (float)(GG-1);
    Geo g;
    g.ax = (grx >= 0.0f) && (grx <= GM1);
    g.ay = (gry >= 0.0f) && (gry <= GM1);
    g.az = (grz >= 0.0f) && (grz <= GM1);
    float gcx = fminf(fmaxf(grx,0.0f), GM1);
    float gcy = fminf(fmaxf(gry,0.0f), GM1);
    float gcz = fminf(fmaxf(grz,0.0f), GM1);
    int ix = min((int)gcx, GG-2);
    int iy = min((int)gcy, GG-2);
    int iz = min((int)gcz, GG-2);
    g.fx = gcx - (float)ix;
    g.fy = gcy - (float)iy;
    g.fz = gcz - (float)iz;
    g.base = ((ix*GG + iy)*GG + iz)*EE;

    u64 ep[8];
    #pragma unroll
    for (int i = 0; i < 8; ++i) ep[i] = 0ull;
    #pragma unroll
    for (int dx = 0; dx < 2; ++dx){
      const float wxv = dx ? g.fx : (1.0f - g.fx);
      #pragma unroll
      for (int dy = 0; dy < 2; ++dy){
        const float wyv = dy ? g.fy : (1.0f - g.fy);
        const ulonglong2* gp = (const ulonglong2*)(grid + g.base + dx*SX + dy*SY);
        const float w0 = wxv*wyv*(1.0f - g.fz);
        const float w1 = wxv*wyv*g.fz;
        const u64 w0p = pk2(w0,w0), w1p = pk2(w1,w1);
        #pragma unroll
        for (int i = 0; i < 4; ++i){
          ulonglong2 a = gp[i];
          ep[2*i]   = ffma2(w0p, a.x, ep[2*i]);
          ep[2*i+1] = ffma2(w0p, a.y, ep[2*i+1]);
        }
        #pragma unroll
        for (int i = 0; i < 4; ++i){
          ulonglong2 b = gp[4+i];
          ep[2*i]   = ffma2(w1p, b.x, ep[2*i]);
          ep[2*i+1] = ffma2(w1p, b.y, ep[2*i+1]);
        }
      }
    }
    if (pi){ gB=g;
      #pragma unroll
      for (int i=0;i<8;++i) epB[i]=ep[i];
    } else { gA=g;
      #pragma unroll
      for (int i=0;i<8;++i) epA[i]=ep[i];
    }
  }

  // warp-uniform color-skip flags: fully-masked halves contribute exactly 0 to 'rendered'
  const bool inA = gA.ax && gA.ay && gA.az;
  const bool inB = gB.ax && gB.ay && gB.az;
  const bool skipA = __all_sync(0xffffffffu, !inA);
  const bool skipB = __all_sync(0xffffffffu, !inB);

  // ---- SDF layers 1+2 fused, k-blocked (KB=4) ----
  u64 h2A[32], h2B[32];
  #pragma unroll
  for (int j = 0; j < 32; ++j){
    u64 b = ((const u64*)(sm + OFF_B2))[j];
    h2A[j]=b; h2B[j]=b;
  }

  #pragma unroll 1
  for (int kb = 0; kb < 64; kb += 4){
    // phase 1: 4 independent z dot-chains
    u64 zab[4];
    #pragma unroll
    for (int t = 0; t < 4; ++t){
      const ulonglong2* w1p = (const ulonglong2*)(sm + OFF_W1 + (kb+t)*16);
      ulonglong2 wa=w1p[0], wb=w1p[1], wc=w1p[2], wd=w1p[3];
      const float b1 = sm[OFF_B1+kb+t];
      u64 zA0=0ull, zA1=0ull, zB0=0ull, zB1=0ull;
      zA0=ffma2(wa.x,epA[0],zA0); zA1=ffma2(wa.y,epA[1],zA1);
      zA0=ffma2(wb.x,epA[2],zA0); zA1=ffma2(wb.y,epA[3],zA1);
      zA0=ffma2(wc.x,epA[4],zA0); zA1=ffma2(wc.y,epA[5],zA1);
      zA0=ffma2(wd.x,epA[6],zA0); zA1=ffma2(wd.y,epA[7],zA1);
      zB0=ffma2(wa.x,epB[0],zB0); zB1=ffma2(wa.y,epB[1],zB1);
      zB0=ffma2(wb.x,epB[2],zB0); zB1=ffma2(wb.y,epB[3],zB1);
      zB0=ffma2(wc.x,epB[4],zB0); zB1=ffma2(wc.y,epB[5],zB1);
      zB0=ffma2(wd.x,epB[6],zB0); zB1=ffma2(wd.y,epB[7],zB1);
      float2 a0=upk2(zA0), a1=upk2(zA1), b0=upk2(zB0), b1v=upk2(zB1);
      zab[t] = pk2(b1 + ((a0.x+a1.x)+(a0.y+a1.y)),
                   b1 + ((b0.x+b1v.x)+(b0.y+b1v.y)));
    }
    // phase 2: activations (independent MUFU chains) + scratch store
    u64 hsp[4];
    #pragma unroll
    for (int t = 0; t < 4; ++t){
      float2 z = upk2(zab[t]);
      float hA = softplus_raw(z.x);
      float hB = softplus_raw(z.y);
      s1p[(kb+t)*TPB] = pk2(dact1(hA), dact1(hB));
      hsp[t] = pk2(hA,hB);
    }
    // phase 3: 4x32 independent ffma2 accumulation
    #pragma unroll
    for (int t = 0; t < 4; ++t){
      float2 h = upk2(hsp[t]);
      const u64 hAp = pk2(h.x,h.x), hBp = pk2(h.y,h.y);
      const ulonglong2* w2p = (const ulonglong2*)(cW2T + (kb+t)*64);
      #pragma unroll
      for (int q = 0; q < 16; ++q){
        ulonglong2 wv = w2p[q];
        h2A[2*q]   = ffma2(wv.x, hAp, h2A[2*q]);
        h2A[2*q+1] = ffma2(wv.y, hAp, h2A[2*q+1]);
        h2B[2*q]   = ffma2(wv.x, hBp, h2B[2*q]);
        h2B[2*q+1] = ffma2(wv.y, hBp, h2B[2*q+1]);
      }
    }
  }
  // activation in place (h2' = softplus(100 z2))
  #pragma unroll
  for (int j = 0; j < 32; ++j){
    float2 ta = upk2(h2A[j]); h2A[j] = pk2(softplus_raw(ta.x), softplus_raw(ta.y));
    float2 tb = upk2(h2B[j]); h2B[j] = pk2(softplus_raw(tb.x), softplus_raw(tb.y));
  }

  // ---- layer 3: sdf (row 0) always, feat rows only where the color MLP will run ----
  // cW3 is 0.01-prescaled; h2' is 100x -> products land at original scale.
  float sdfA, sdfB;
  float featA[15], featB[15];
  {
    const ulonglong2* w = (const ulonglong2*)(cW3);
    u64 aA0=0ull,aA1=0ull,aB0=0ull,aB1=0ull;
    #pragma unroll
    for (int q = 0; q < 16; ++q){
      ulonglong2 wv = w[q];
      aA0 = ffma2(wv.x, h2A[2*q],   aA0);
      aA1 = ffma2(wv.y, h2A[2*q+1], aA1);
      aB0 = ffma2(wv.x, h2B[2*q],   aB0);
      aB1 = ffma2(wv.y, h2B[2*q+1], aB1);
    }
    float bias = sm[OFF_B3];
    float2 ta0=upk2(aA0), ta1=upk2(aA1), tb0=upk2(aB0), tb1=upk2(aB1);
    sdfA = bias + ((ta0.x+ta1.x)+(ta0.y+ta1.y));
    sdfB = bias + ((tb0.x+tb1.x)+(tb0.y+tb1.y));
  }
  if (!skipA && !skipB){
    #pragma unroll 2
    for (int c = 1; c < 16; ++c){
      const ulonglong2* w = (const ulonglong2*)(cW3 + c*64);
      u64 aA0=0ull,aA1=0ull,aB0=0ull,aB1=0ull;
      #pragma unroll
      for (int q = 0; q < 16; ++q){
        ulonglong2 wv = w[q];
        aA0 = ffma2(wv.x, h2A[2*q],   aA0);
        aA1 = ffma2(wv.y, h2A[2*q+1], aA1);
        aB0 = ffma2(wv.x, h2B[2*q],   aB0);
        aB1 = ffma2(wv.y, h2B[2*q+1], aB1);
      }
      float bias = sm[OFF_B3+c];
      float2 ta0=upk2(aA0), ta1=upk2(aA1), tb0=upk2(aB0), tb1=upk2(aB1);
      featA[c-1] = bias + ((ta0.x+ta1.x)+(ta0.y+ta1.y));
      featB[c-1] = bias + ((tb0.x+tb1.x)+(tb0.y+tb1.y));
    }
  } else if (!skipA || !skipB){
    const u64* h2 = skipB ? h2A : h2B;
    float* feat   = skipB ? featA : featB;
    #pragma unroll 2
    for (int c = 1; c < 16; ++c){
      const ulonglong2* w = (const ulonglong2*)(cW3 + c*64);
      u64 a0=0ull, a1=0ull;
      #pragma unroll
      for (int q = 0; q < 16; ++q){
        ulonglong2 wv = w[q];
        a0 = ffma2(wv.x, h2[2*q],   a0);
        a1 = ffma2(wv.y, h2[2*q+1], a1);
      }
      float bias = sm[OFF_B3+c];
      float2 t0=upk2(a0), t1=upk2(a1);
      feat[c-1] = bias + ((t0.x+t1.x)+(t0.y+t1.y));
    }
  }

  // ---- backward: g2' = (0.01 W3[0][:]) * sigmoid(100 z2), overwrite h2 ----
  #pragma unroll
  for (int j = 0; j < 32; ++j){
    u64 w3p = ((const u64*)cW3)[j];
    float2 ta = upk2(h2A[j]);
    float2 tb = upk2(h2B[j]);
    h2A[j] = fmul2(w3p, pk2(dact1(ta.x), dact1(ta.y)));
    h2B[j] = fmul2(w3p, pk2(dact1(tb.x), dact1(tb.y)));
  }

  u64 deA[8], deB[8];
  #pragma unroll
  for (int i = 0; i < 8; ++i){ deA[i]=0ull; deB[i]=0ull; }

  #pragma unroll 1
  for (int kb = 0; kb < 64; kb += 4){
    // phase 1: 4 independent GEMV sum chains
    u64 sums[4];
    #pragma unroll
    for (int t = 0; t < 4; ++t){
      const ulonglong2* w2p = (const ulonglong2*)(cW2T + (kb+t)*64);
      u64 aA0=0ull,aA1=0ull,aB0=0ull,aB1=0ull;
      #pragma unroll
      for (int q = 0; q < 16; ++q){
        ulonglong2 wv = w2p[q];
        aA0 = ffma2(wv.x, h2A[2*q],   aA0);
        aA1 = ffma2(wv.y, h2A[2*q+1], aA1);
        aB0 = ffma2(wv.x, h2B[2*q],   aB0);
        aB1 = ffma2(wv.y, h2B[2*q+1], aB1);
      }
      float2 ta0=upk2(aA0), ta1=upk2(aA1), tb0=upk2(aB0), tb1=upk2(aB1);
      sums[t] = pk2((ta0.x+ta1.x)+(ta0.y+ta1.y),
                    (tb0.x+tb1.x)+(tb0.y+tb1.y));
    }
    // phase 2: dz = sums * stored-sigmoid (packed mul)
    u64 dz[4];
    #pragma unroll
    for (int t = 0; t < 4; ++t) dz[t] = fmul2(sums[t], s1p[(kb+t)*TPB]);
    // phase 3: de accumulation (independent)
    #pragma unroll
    for (int t = 0; t < 4; ++t){
      float2 d = upk2(dz[t]);
      const u64 dzAp = pk2(d.x,d.x), dzBp = pk2(d.y,d.y);
      const ulonglong2* w1p = (const ulonglong2*)(sm + OFF_W1 + (kb+t)*16);
      ulonglong2 wa=w1p[0], wb=w1p[1], wc=w1p[2], wd=w1p[3];
      deA[0]=ffma2(dzAp,wa.x,deA[0]); deA[1]=ffma2(dzAp,wa.y,deA[1]);
      deA[2]=ffma2(dzAp,wb.x,deA[2]); deA[3]=ffma2(dzAp,wb.y,deA[3]);
      deA[4]=ffma2(dzAp,wc.x,deA[4]); deA[5]=ffma2(dzAp,wc.y,deA[5]);
      deA[6]=ffma2(dzAp,wd.x,deA[6]); deA[7]=ffma2(dzAp,wd.y,deA[7]);
      deB[0]=ffma2(dzBp,wa.x,deB[0]); deB[1]=ffma2(dzBp,wa.y,deB[1]);
      deB[2]=ffma2(dzBp,wb.x,deB[2]); deB[3]=ffma2(dzBp,wb.y,deB[3]);
      deB[4]=ffma2(dzBp,wc.x,deB[4]); deB[5]=ffma2(dzBp,wc.y,deB[5]);
      deB[6]=ffma2(dzBp,wd.x,deB[6]); deB[7]=ffma2(dzBp,wd.y,deB[7]);
    }
  }

  // ---- re-gather corners (packed dot) -> spatial gradient; normals ----
  // de is 1e-4-scaled (both W2T and W3 prescaled by 0.01) -> fold 1e4 into SCALE.
  float nxA,nyA,nzA, nxB,nyB,nzB;
  #pragma unroll
  for (int pi = 0; pi < PPT; ++pi){
    const Geo g = pi ? gB : gA;
    const u64* de = pi ? deB : deA;
    float gx=0.f, gy=0.f, gz=0.f;
    #pragma unroll
    for (int dx = 0; dx < 2; ++dx){
      const float wxv = dx ? g.fx : (1.0f - g.fx);
      #pragma unroll
      for (int dy = 0; dy < 2; ++dy){
        const float wyv = dy ? g.fy : (1.0f - g.fy);
        const ulonglong2* gp = (const ulonglong2*)(grid + g.base + dx*SX + dy*SY);
        u64 acc0=0ull, acc1=0ull;
        #pragma unroll
        for (int i = 0; i < 4; ++i){
          ulonglong2 a = gp[i];
          acc0 = ffma2(a.x, de[2*i],   acc0);
          acc0 = ffma2(a.y, de[2*i+1], acc0);
        }
        #pragma unroll
        for (int i = 0; i < 4; ++i){
          ulonglong2 b = gp[4+i];
          acc1 = ffma2(b.x, de[2*i],   acc1);
          acc1 = ffma2(b.y, de[2*i+1], acc1);
        }
        float2 t0 = upk2(acc0), t1 = upk2(acc1);
        float sA = t0.x + t0.y;
        float sB = t1.x + t1.y;
        float sc = fmaf(g.fz, sB - sA, sA);
        gz = fmaf(wxv*wyv, sB - sA, gz);
        gx += dx ? wyv*sc : -wyv*sc;
        gy += dy ? wxv*sc : -wxv*sc;
      }
    }
    const float SCALE = 0.5f*(float)(GG-1)/1.3f * 10000.0f;  // 1e4 compensates prescale
    const float Gx = g.ax ? gx*SCALE : 0.0f;
    const float Gy = g.ay ? gy*SCALE : 0.0f;
    const float Gz = g.az ? gz*SCALE : 0.0f;
    const int p = pi ? pB : pA;
    out_grads[3*p+0] = Gx;
    out_grads[3*p+1] = Gy;
    out_grads[3*p+2] = Gz;
    const float nn = sqrtf(Gx*Gx + Gy*Gy + Gz*Gz);
    const float inv = 1.0f / fmaxf(nn, 1e-12f);
    if (pi){ nxB=Gx*inv; nyB=Gy*inv; nzB=Gz*inv; }
    else   { nxA=Gx*inv; nyA=Gy*inv; nzA=Gz*inv; }
  }

  // ---- color MLP, j-blocked (KB=4): skip fully-masked halves ----
  float rgbA[3] = {0.f,0.f,0.f}, rgbB[3] = {0.f,0.f,0.f};

  if (!skipA && !skipB){
    u64 ciA[9], ciB[9];
    #pragma unroll
    for (int i = 0; i < 7; ++i){
      ciA[i] = pk2(featA[2*i], featA[2*i+1]);
      ciB[i] = pk2(featB[2*i], featB[2*i+1]);
    }
    ciA[7] = pk2(featA[14], nxA); ciA[8] = pk2(nyA, nzA);
    ciB[7] = pk2(featB[14], nxB); ciB[8] = pk2(nyB, nzB);

    #pragma unroll
    for (int j = 0; j < 32; ++j){
      u64 b = ((const u64*)(sm + OFF_CB2))[j];
      h2A[j]=b; h2B[j]=b;
    }

    #pragma unroll 1
    for (int jb = 0; jb < 64; jb += 4){
      // phase 1: 4 independent c1 dot-chains
      u64 cab[4];
      #pragma unroll
      for (int t = 0; t < 4; ++t){
        const ulonglong2* w = (const ulonglong2*)(sm + OFF_CW1P + (jb+t)*24);
        ulonglong2 wa=w[0], wb=w[1], wc=w[2], wd=w[3];
        u64 w8 = ((const u64*)(sm + OFF_CW1P + (jb+t)*24))[8];
        const float bias = sm[OFF_CB1+jb+t];
        u64 zA0=0ull, zA1=0ull, zB0=0ull, zB1=0ull;
        zA0=ffma2(wa.x,ciA[0],zA0); zA1=ffma2(wa.y,ciA[1],zA1);
        zA0=ffma2(wb.x,ciA[2],zA0); zA1=ffma2(wb.y,ciA[3],zA1);
        zA0=ffma2(wc.x,ciA[4],zA0); zA1=ffma2(wc.y,ciA[5],zA1);
        zA0=ffma2(wd.x,ciA[6],zA0); zA1=ffma2(wd.y,ciA[7],zA1);
        zA0=ffma2(w8,  ciA[8],zA0);
        zB0=ffma2(wa.x,ciB[0],zB0); zB1=ffma2(wa.y,ciB[1],zB1);
        zB0=ffma2(wb.x,ciB[2],zB0); zB1=ffma2(wb.y,ciB[3],zB1);
        zB0=ffma2(wc.x,ciB[4],zB0); zB1=ffma2(wc.y,ciB[5],zB1);
        zB0=ffma2(wd.x,ciB[6],zB0); zB1=ffma2(wd.y,ciB[7],zB1);
        zB0=ffma2(w8,  ciB[8],zB0);
        float2 ta0=upk2(zA0), ta1=upk2(zA1), tb0=upk2(zB0), tb1=upk2(zB1);
        cab[t] = pk2(fmaxf(bias + ((ta0.x+ta1.x)+(ta0.y+ta1.y)), 0.0f),
                     fmaxf(bias + ((tb0.x+tb1.x)+(tb0.y+tb1.y)), 0.0f));
      }
      // phase 2: accumulate
      #pragma unroll
      for (int t = 0; t < 4; ++t){
        float2 c = upk2(cab[t]);
        const u64 cAp = pk2(c.x,c.x), cBp = pk2(c.y,c.y);
        const ulonglong2* wt = (const ulonglong2*)(cCW2T + (jb+t)*64);
        #pragma unroll
        for (int q = 0; q < 16; ++q){
          ulonglong2 wv = wt[q];
          h2A[2*q]   = ffma2(wv.x, cAp, h2A[2*q]);
          h2A[2*q+1] = ffma2(wv.y, cAp, h2A[2*q+1]);
          h2B[2*q]   = ffma2(wv.x, cBp, h2B[2*q]);
          h2B[2*q+1] = ffma2(wv.y, cBp, h2B[2*q+1]);
        }
      }
    }
    #pragma unroll
    for (int j = 0; j < 32; ++j){
      float2 ta = upk2(h2A[j]); h2A[j] = pk2(fmaxf(ta.x,0.0f), fmaxf(ta.y,0.0f));
      float2 tb = upk2(h2B[j]); h2B[j] = pk2(fmaxf(tb.x,0.0f), fmaxf(tb.y,0.0f));
    }

    #pragma unroll 2
    for (int c = 0; c < 3; ++c){
      const ulonglong2* w = (const ulonglong2*)(cCW3 + c*64);
      u64 aA0=0ull,aA1=0ull,aB0=0ull,aB1=0ull;
      #pragma unroll
      for (int q = 0; q < 16; ++q){
        ulonglong2 wv = w[q];
        aA0 = ffma2(wv.x, h2A[2*q],   aA0);
        aA1 = ffma2(wv.y, h2A[2*q+1], aA1);
        aB0 = ffma2(wv.x, h2B[2*q],   aB0);
        aB1 = ffma2(wv.y, h2B[2*q+1], aB1);
      }
      float bias = sm[OFF_CB3+c];
      float2 ta0=upk2(aA0), ta1=upk2(aA1), tb0=upk2(aB0), tb1=upk2(aB1);
      rgbA[c] = 1.0f / (1.0f + __expf(-(bias + ((ta0.x+ta1.x)+(ta0.y+ta1.y)))));
      rgbB[c] = 1.0f / (1.0f + __expf(-(bias + ((tb0.x+tb1.x)+(tb0.y+tb1.y)))));
    }
  } else if (!skipA || !skipB){
    // one half fully masked -> single-point color path for the live half
    u64 ci[9];
    const float* feat = skipB ? featA : featB;
    const float nx = skipB ? nxA : nxB;
    const float ny = skipB ? nyA : nyB;
    const float nz = skipB ? nzA : nzB;
    #pragma unroll
    for (int i = 0; i < 7; ++i) ci[i] = pk2(feat[2*i], feat[2*i+1]);
    ci[7] = pk2(feat[14], nx); ci[8] = pk2(ny, nz);
    float rgb[3];
    color_single(sm, ci, h2A, rgb);
    if (skipB){ rgbA[0]=rgb[0]; rgbA[1]=rgb[1]; rgbA[2]=rgb[2]; }
    else      { rgbB[0]=rgb[0]; rgbB[1]=rgb[1]; rgbB[2]=rgb[2]; }
  }
  // both skipped: rgb stays 0 (multiplied by exactly-zero weights downstream)

  // ---- sigma (Laplace CDF) + stores ----
  const float bet = 0.015f + fabsf(beta_p[0]);
  {
    const float s = sdfA;
    const float sgn = (s > 0.0f) ? 1.0f : ((s < 0.0f) ? -1.0f : 0.0f);
    float sigma = (0.5f + 0.5f*sgn*expm1f(-fabsf(s)/bet)) / bet;
    if (!inA) sigma = 0.0f;
    g_srgb[pA] = make_float4(sigma, rgbA[0], rgbA[1], rgbA[2]);
    g_nrm[pA]  = make_float4(nxA, nyA, nzA, 0.0f);
  }
  {
    const float s = sdfB;
    const float sgn = (s > 0.0f) ? 1.0f : ((s < 0.0f) ? -1.0f : 0.0f);
    float sigma = (0.5f + 0.5f*sgn*expm1f(-fabsf(s)/bet)) / bet;
    if (!inB) sigma = 0.0f;
    g_srgb[pB] = make_float4(sigma, rgbB[0], rgbB[1], rgbB[2]);
    g_nrm[pB]  = make_float4(nxB, nyB, nzB, 0.0f);
  }
}

// ---- per-ray compositing: one warp per ray, 2 samples per lane ----
__global__ void __launch_bounds__(256)
k_render(const float* __restrict__ rdn,
         const unsigned* __restrict__ near_p, const unsigned* __restrict__ far_p,
         float* __restrict__ out)
{
  const int gt = blockIdx.x*256 + threadIdx.x;
  const int r = gt >> 5;
  const int lane = gt & 31;
  if (r >= RR) return;

  const float nearf = decode_scalar(near_p);
  const float farf  = decode_scalar(far_p);
  const float span  = farf - nearf;
  const float dt    = span * (1.0f/64.0f);

  const int p0 = r*64 + lane, p1 = p0 + 32;
  float4 a0 = g_srgb[p0], a1 = g_srgb[p1];
  float4 n0 = g_nrm[p0],  n1 = g_nrm[p1];
  const float dd0 = a0.x * dt;
  const float dd1 = a1.x * dt;

  float cs0 = dd0;
  #pragma unroll
  for (int o = 1; o < 32; o <<= 1){ float v = __shfl_up_sync(0xffffffffu, cs0, o); if (lane >= o) cs0 += v; }
  const float tot0 = __shfl_sync(0xffffffffu, cs0, 31);
  float cs1 = dd1;
  #pragma unroll
  for (int o = 1; o < 32; o <<= 1){ float v = __shfl_up_sync(0xffffffffu, cs1, o); if (lane >= o) cs1 += v; }
  cs1 += tot0;

  const float T0 = __expf(dd0 - cs0);
  const float T1 = __expf(dd1 - cs1);
  const float w0 = (1.0f - __expf(-dd0)) * T0;
  const float w1 = (1.0f - __expf(-dd1)) * T1;
  const float tm0 = nearf + span * (((float)lane + 0.5f)  * (1.0f/64.0f));
  const float tm1 = nearf + span * (((float)lane + 32.5f) * (1.0f/64.0f));

  float v0 = w0*a0.y + w1*a1.y;
  float v1 = w0*a0.z + w1*a1.z;
  float v2 = w0*a0.w + w1*a1.w;
  float v3 = w0*tm0  + w1*tm1;
  float v4 = w0*n0.x + w1*n1.x;
  float v5 = w0*n0.y + w1*n1.y;
  float v6 = w0*n0.z + w1*n1.z;
  float v7 = w0 + w1;

  #pragma unroll
  for (int o = 16; o > 0; o >>= 1){
    v0 += __shfl_down_sync(0xffffffffu, v0, o);
    v1 += __shfl_down_sync(0xffffffffu, v1, o);
    v2 += __shfl_down_sync(0xffffffffu, v2, o);
    v3 += __shfl_down_sync(0xffffffffu, v3, o);
    v4 += __shfl_down_sync(0xffffffffu, v4, o);
    v5 += __shfl_down_sync(0xffffffffu, v5, o);
    v6 += __shfl_down_sync(0xffffffffu, v6, o);
    v7 += __shfl_down_sync(0xffffffffu, v7, o);
  }
  if (lane == 0){
    float* op = out + r*8;
    op[0]=v0; op[1]=v1; op[2]=v2;
    op[3]=v3 / rdn[r];
    op[4]=v4; op[5]=v5; op[6]=v6; op[7]=v7;
  }
}

extern "C" void kernel_launch(void* const* d_in, const int* in_sizes, int n_in,
                              void* d_out, int out_size)
{
  const float* rays_o = (const float*)d_in[0];
  const float* rays_d = (const float*)d_in[1];
  const float* rdn    = (const float*)d_in[2];
  const float* grid   = (const float*)d_in[3];
  const float* sw1 = (const float*)d_in[4];
  const float* sb1 = (const float*)d_in[5];
  const float* sw2 = (const float*)d_in[6];
  const float* sb2 = (const float*)d_in[7];
  const float* sw3 = (const float*)d_in[8];
  const float* sb3 = (const float*)d_in[9];
  const float* cw1 = (const float*)d_in[10];
  const float* cb1 = (const float*)d_in[11];
  const float* cw2 = (const float*)d_in[12];
  const float* cb2 = (const float*)d_in[13];
  const float* cw3 = (const float*)d_in[14];
  const float* cb3 = (const float*)d_in[15];
  const float* beta = (const float*)d_in[16];
  const unsigned* nearp = (const unsigned*)d_in[17];
  const unsigned* farp  = (const unsigned*)d_in[18];

  float* out = (float*)d_out;
  float* out_grads = out + RR*8;   // output = [rendered (R,8), sdf_grads (R*S,3)]

  // Resolve constant-bank addresses (pure address queries; no stream work).
  void *w2t_p = nullptr, *cw2t_p = nullptr, *w3_p = nullptr, *cw3_p = nullptr;
  cudaGetSymbolAddress(&w2t_p,  cW2T);
  cudaGetSymbolAddress(&cw2t_p, cCW2T);
  cudaGetSymbolAddress(&w3_p,   cW3);
  cudaGetSymbolAddress(&cw3_p,  cCW3);

  cudaFuncSetAttribute(k_points, cudaFuncAttributeMaxDynamicSharedMemorySize, SMEM_BYTES);

  // 1) prep kernel writes (prescaled) transposed weights into the constant bank
  k_prep<<<1, 256>>>(sw2, cw2, sw3, cw3,
                     (float*)w2t_p, (float*)cw2t_p, (float*)w3_p, (float*)cw3_p);

  // 2) main point kernel + compositing
  k_points<<<RR/4, TPB, SMEM_BYTES>>>(
      rays_o, rays_d, grid,
      sw1, sb1, sb2, sb3,
      cw1, cb1, cb2, cb3,
      beta, nearp, farp, out_grads);

  k_render<<<(RR*32)/256, 256>>>(rdn, nearp, farp, out);
}

// round 17
// speedup vs baseline: 1.0441x; 1.0441x over previous
#include <cuda_runtime.h>

#define RR 16384
#define SS 64
#define GG 128
#define EE 16
#define NPTS (RR*SS)
#define SX (GG*GG*EE)
#define SY (GG*EE)
#define TPB 128
#define PPT 2            // points per thread (A = s0-31, B = s32-63 of the SAME ray)

typedef unsigned long long u64;

// ---- scratch (per-point) ----
__device__ float4 g_srgb[NPTS];   // (sigma, r, g, b)
__device__ float4 g_nrm[NPTS];    // (nx, ny, nz, 0)

// Large streaming matrices in the constant bank (uniform-port loads).
// cW2T and cW3 are PRESCALED by 0.01 in k_prep (activation 100x-scale algebra).
__constant__ __align__(16) float cW2T[4096];   // [k][j] = 0.01*sw2[j][k]
__constant__ __align__(16) float cCW2T[4096];  // [k][j] = cw2[j][k]   (unscaled)
__constant__ __align__(16) float cW3[1024];    // 0.01 * (16x64 row-major)
__constant__ __align__(16) float cCW3[192];    // 3x64 row-major       (unscaled)

// ---- packed f32x2 helpers ----
__device__ __forceinline__ u64 pk2(float a, float b){
  u64 r; asm("mov.b64 %0, {%1,%2};" : "=l"(r) : "f"(a), "f"(b)); return r;
}
__device__ __forceinline__ float2 upk2(u64 v){
  float2 t; asm("mov.b64 {%0,%1}, %2;" : "=f"(t.x), "=f"(t.y) : "l"(v)); return t;
}
__device__ __forceinline__ u64 ffma2(u64 a, u64 b, u64 c){
  u64 r; asm("fma.rn.f32x2 %0, %1, %2, %3;" : "=l"(r) : "l"(a), "l"(b), "l"(c)); return r;
}
__device__ __forceinline__ u64 fmul2(u64 a, u64 b){
  u64 r; asm("mul.rn.f32x2 %0, %1, %2;" : "=l"(r) : "l"(a), "l"(b)); return r;
}

__device__ __forceinline__ float decode_scalar(const unsigned* p){
  unsigned u = *p;
  if (u == 0u) return 0.0f;
  if ((u >> 23) == 0u) return (float)(int)u;   // small integer bit pattern
  return __uint_as_float(u);
}
// softplus(100 z)  (NOT divided by 100 — downstream weights are prescaled)
__device__ __forceinline__ float softplus_raw(float z){
  float y = 100.0f*z;
  float t = __expf(-fabsf(y));
  return fmaxf(y,0.0f) + __logf(1.0f + t);
}
// sigmoid(100 z) from h' = softplus(100 z)
__device__ __forceinline__ float dact1(float h){ return 1.0f - __expf(-h); }

// ---- shared layout (float offsets; dynamic smem) ----
#define OFF_W1    0      // 1024  (64x16 row-major)
#define OFF_B1    1024   // 64
#define OFF_B2    1088   // 64
#define OFF_B3    1152   // 16
#define OFF_CW1P  1168   // 1536  (64x24, rows zero-padded from 18)
#define OFF_CB1   2704   // 64
#define OFF_CB2   2768   // 64
#define OFF_CB3   2832   // 3
#define OFF_S1    2840   // 64*TPB u64 per-thread scratch (16B aligned)
#define SM_FLOATS (OFF_S1 + 64*TPB*2)
#define SMEM_BYTES (SM_FLOATS*4)

struct Geo {
  float fx, fy, fz;
  int base;
  bool ax, ay, az;
};

// ---- prep: transposed / raw weights into the constant bank (with prescale) ----
__global__ void k_prep(const float* __restrict__ sw2, const float* __restrict__ cw2,
                       const float* __restrict__ sw3, const float* __restrict__ cw3,
                       float* __restrict__ dW2T, float* __restrict__ dCW2T,
                       float* __restrict__ dW3, float* __restrict__ dCW3)
{
  for (int i = threadIdx.x; i < 4096; i += blockDim.x){
    int j = i >> 6, k = i & 63;
    dW2T [k*64 + j] = 0.01f * sw2[i];
    dCW2T[k*64 + j] = cw2[i];
  }
  for (int i = threadIdx.x; i < 1024; i += blockDim.x) dW3[i] = 0.01f * sw3[i];
  for (int i = threadIdx.x; i < 192;  i += blockDim.x) dCW3[i] = cw3[i];
}

// ---- single-point color MLP (used when the partner point is fully masked) ----
__device__ __forceinline__ void color_single(const float* sm, const u64* ci,
                                             u64* acc /*32*/, float* rgb)
{
  #pragma unroll
  for (int j = 0; j < 32; ++j) acc[j] = ((const u64*)(sm + OFF_CB2))[j];

  #pragma unroll 1
  for (int j = 0; j < 64; ++j){
    const ulonglong2* w = (const ulonglong2*)(sm + OFF_CW1P + j*24);
    ulonglong2 wa=w[0], wb=w[1], wc=w[2], wd=w[3];
    u64 w8 = ((const u64*)(sm + OFF_CW1P + j*24))[8];
    const float bias = sm[OFF_CB1+j];
    u64 z0=0ull, z1=0ull;
    z0=ffma2(wa.x,ci[0],z0); z1=ffma2(wa.y,ci[1],z1);
    z0=ffma2(wb.x,ci[2],z0); z1=ffma2(wb.y,ci[3],z1);
    z0=ffma2(wc.x,ci[4],z0); z1=ffma2(wc.y,ci[5],z1);
    z0=ffma2(wd.x,ci[6],z0); z1=ffma2(wd.y,ci[7],z1);
    z0=ffma2(w8,  ci[8],z0);
    float2 t0=upk2(z0), t1=upk2(z1);
    float z = bias + ((t0.x+t1.x)+(t0.y+t1.y));
    float c1 = fmaxf(z, 0.0f);
    const u64 cp = pk2(c1,c1);
    const ulonglong2* wt = (const ulonglong2*)(cCW2T + j*64);
    #pragma unroll
    for (int q = 0; q < 16; ++q){
      ulonglong2 wv = wt[q];
      acc[2*q]   = ffma2(wv.x, cp, acc[2*q]);
      acc[2*q+1] = ffma2(wv.y, cp, acc[2*q+1]);
    }
  }
  #pragma unroll
  for (int j = 0; j < 32; ++j){
    float2 t = upk2(acc[j]); acc[j] = pk2(fmaxf(t.x,0.0f), fmaxf(t.y,0.0f));
  }
  #pragma unroll 1
  for (int c = 0; c < 3; ++c){
    const ulonglong2* w = (const ulonglong2*)(cCW3 + c*64);
    u64 a0=0ull, a1=0ull;
    #pragma unroll
    for (int q = 0; q < 16; ++q){
      ulonglong2 wv = w[q];
      a0 = ffma2(wv.x, acc[2*q],   a0);
      a1 = ffma2(wv.y, acc[2*q+1], a1);
    }
    float bias = sm[OFF_CB3+c];
    float2 t0=upk2(a0), t1=upk2(a1);
    rgb[c] = 1.0f / (1.0f + __expf(-(bias + ((t0.x+t1.x)+(t0.y+t1.y)))));
  }
}

__global__ void __launch_bounds__(TPB, 2)
k_points(const float* __restrict__ rays_o, const float* __restrict__ rays_d,
         const float* __restrict__ grid,
         const float* __restrict__ sw1, const float* __restrict__ sb1,
         const float* __restrict__ sb2, const float* __restrict__ sb3,
         const float* __restrict__ cw1, const float* __restrict__ cb1,
         const float* __restrict__ cb2, const float* __restrict__ cb3,
         const float* __restrict__ beta_p,
         const unsigned* __restrict__ near_p, const unsigned* __restrict__ far_p,
         float* __restrict__ out_grads)
{
  extern __shared__ __align__(16) float sm[];
  const int tid = threadIdx.x;

  // ---- cooperative staging of SMALL arrays ----
  for (int i = tid; i < 1024; i += TPB) sm[OFF_W1+i]=sw1[i];
  for (int i = tid; i < 1536; i += TPB) sm[OFF_CW1P+i] = 0.0f;
  if (tid < 64){ sm[OFF_B1+tid]=sb1[tid]; sm[OFF_B2+tid]=sb2[tid];
                 sm[OFF_CB1+tid]=cb1[tid]; sm[OFF_CB2+tid]=cb2[tid]; }
  if (tid < 16) sm[OFF_B3+tid]=sb3[tid];
  if (tid < 3)  sm[OFF_CB3+tid]=cb3[tid];
  __syncthreads();
  for (int i = tid; i < 1152; i += TPB){
    int j = i / 18, c = i - j*18;
    sm[OFF_CW1P + j*24 + c] = cw1[i];
  }
  __syncthreads();

  u64* s1p = ((u64*)(sm + OFF_S1)) + tid;   // per-thread scratch, stride TPB per k

  // warp = one ray; lane l: A = sample l, B = sample l+32
  const int wid  = tid >> 5;
  const int lane = tid & 31;
  const int ray  = blockIdx.x*4 + wid;
  const int pA = ray*64 + lane;
  const int pB = pA + 32;

  const float nearf = decode_scalar(near_p);
  const float farf  = decode_scalar(far_p);
  const float span  = farf - nearf;

  // ---- geometry + forward gather (packed embeddings: 8 pairs per point) ----
  Geo gA, gB;
  u64 epA[8], epB[8];

  #pragma unroll
  for (int pi = 0; pi < PPT; ++pi){
    const int p = pi ? pB : pA;
    const int s = p & 63;
    const float tm = nearf + span * ((s + 0.5f) * (1.0f/64.0f));
    const float px = fmaf(tm, rays_d[3*ray+0], rays_o[3*ray+0]);
    const float py = fmaf(tm, rays_d[3*ray+1], rays_o[3*ray+1]);
    const float pz = fmaf(tm, rays_d[3*ray+2], rays_o[3*ray+2]);

    const float HALF = 0.5f*(float)(GG-1);
    float grx = (px*(1.0f/1.3f) + 1.0f)*HALF;
    float gry = (py*(1.0f/1.3f) + 1.0f)*HALF;
    float grz = (pz*(1.0f/1.3f) + 1.0f)*HALF;
    const float GM1 = (float)(GG-1);
    Geo g;
    g.ax = (grx >= 0.0f) && (grx <= GM1);
    g.ay = (gry >= 0.0f) && (gry <= GM1);
    g.az = (grz >= 0.0f) && (grz <= GM1);
    float gcx = fminf(fmaxf(grx,0.0f), GM1);
    float gcy = fminf(fmaxf(gry,0.0f), GM1);
    float gcz = fminf(fmaxf(grz,0.0f), GM1);
    int ix = min((int)gcx, GG-2);
    int iy = min((int)gcy, GG-2);
    int iz = min((int)gcz, GG-2);
    g.fx = gcx - (float)ix;
    g.fy = gcy - (float)iy;
    g.fz = gcz - (float)iz;
    g.base = ((ix*GG + iy)*GG + iz)*EE;

    u64 ep[8];
    #pragma unroll
    for (int i = 0; i < 8; ++i) ep[i] = 0ull;
    #pragma unroll
    for (int dx = 0; dx < 2; ++dx){
      const float wxv = dx ? g.fx : (1.0f - g.fx);
      #pragma unroll
      for (int dy = 0; dy < 2; ++dy){
        const float wyv = dy ? g.fy : (1.0f - g.fy);
        const ulonglong2* gp = (const ulonglong2*)(grid + g.base + dx*SX + dy*SY);
        const float w0 = wxv*wyv*(1.0f - g.fz);
        const float w1 = wxv*wyv*g.fz;
        const u64 w0p = pk2(w0,w0), w1p = pk2(w1,w1);
        #pragma unroll
        for (int i = 0; i < 4; ++i){
          ulonglong2 a = gp[i];
          ep[2*i]   = ffma2(w0p, a.x, ep[2*i]);
          ep[2*i+1] = ffma2(w0p, a.y, ep[2*i+1]);
        }
        #pragma unroll
        for (int i = 0; i < 4; ++i){
          ulonglong2 b = gp[4+i];
          ep[2*i]   = ffma2(w1p, b.x, ep[2*i]);
          ep[2*i+1] = ffma2(w1p, b.y, ep[2*i+1]);
        }
      }
    }
    if (pi){ gB=g;
      #pragma unroll
      for (int i=0;i<8;++i) epB[i]=ep[i];
    } else { gA=g;
      #pragma unroll
      for (int i=0;i<8;++i) epA[i]=ep[i];
    }
  }

  // warp-uniform color-skip flags: fully-masked halves contribute exactly 0 to 'rendered'
  const bool inA = gA.ax && gA.ay && gA.az;
  const bool inB = gB.ax && gB.ay && gB.az;
  const bool skipA = __all_sync(0xffffffffu, !inA);
  const bool skipB = __all_sync(0xffffffffu, !inB);

  // ---- SDF layers 1+2 fused: h2 accumulators packed (32 pairs per point) ----
  u64 h2A[32], h2B[32];
  #pragma unroll
  for (int j = 0; j < 32; ++j){
    u64 b = ((const u64*)(sm + OFF_B2))[j];
    h2A[j]=b; h2B[j]=b;
  }

  #pragma unroll 2
  for (int k = 0; k < 64; ++k){
    const ulonglong2* w1p = (const ulonglong2*)(sm + OFF_W1 + k*16);
    ulonglong2 wa=w1p[0], wb=w1p[1], wc=w1p[2], wd=w1p[3];
    const float b1 = sm[OFF_B1+k];
    u64 zA0=0ull, zA1=0ull, zB0=0ull, zB1=0ull;
    zA0=ffma2(wa.x,epA[0],zA0); zA1=ffma2(wa.y,epA[1],zA1);
    zA0=ffma2(wb.x,epA[2],zA0); zA1=ffma2(wb.y,epA[3],zA1);
    zA0=ffma2(wc.x,epA[4],zA0); zA1=ffma2(wc.y,epA[5],zA1);
    zA0=ffma2(wd.x,epA[6],zA0); zA1=ffma2(wd.y,epA[7],zA1);
    zB0=ffma2(wa.x,epB[0],zB0); zB1=ffma2(wa.y,epB[1],zB1);
    zB0=ffma2(wb.x,epB[2],zB0); zB1=ffma2(wb.y,epB[3],zB1);
    zB0=ffma2(wc.x,epB[4],zB0); zB1=ffma2(wc.y,epB[5],zB1);
    zB0=ffma2(wd.x,epB[6],zB0); zB1=ffma2(wd.y,epB[7],zB1);
    float2 a0=upk2(zA0), a1=upk2(zA1), b0=upk2(zB0), b1v=upk2(zB1);
    float zA = b1 + ((a0.x+a1.x)+(a0.y+a1.y));
    float zB = b1 + ((b0.x+b1v.x)+(b0.y+b1v.y));
    float hA = softplus_raw(zA);
    float hB = softplus_raw(zB);
    // stash sigmoid(100 z1) for the backward pass (per-thread scratch, no sync)
    s1p[k*TPB] = pk2(dact1(hA), dact1(hB));
    const u64 hAp = pk2(hA,hA), hBp = pk2(hB,hB);
    const ulonglong2* w2p = (const ulonglong2*)(cW2T + k*64);
    #pragma unroll
    for (int q = 0; q < 16; ++q){
      ulonglong2 wv = w2p[q];
      h2A[2*q]   = ffma2(wv.x, hAp, h2A[2*q]);
      h2A[2*q+1] = ffma2(wv.y, hAp, h2A[2*q+1]);
      h2B[2*q]   = ffma2(wv.x, hBp, h2B[2*q]);
      h2B[2*q+1] = ffma2(wv.y, hBp, h2B[2*q+1]);
    }
  }
  // activation in place (h2' = softplus(100 z2); z2 landed at original scale)
  #pragma unroll
  for (int j = 0; j < 32; ++j){
    float2 ta = upk2(h2A[j]); h2A[j] = pk2(softplus_raw(ta.x), softplus_raw(ta.y));
    float2 tb = upk2(h2B[j]); h2B[j] = pk2(softplus_raw(tb.x), softplus_raw(tb.y));
  }

  // ---- layer 3: sdf (row 0) always, feat rows only where the color MLP will run ----
  // cW3 is 0.01-prescaled; h2' is 100x -> products land at original scale.
  float sdfA, sdfB;
  float featA[15], featB[15];
  {
    const ulonglong2* w = (const ulonglong2*)(cW3);
    u64 aA0=0ull,aA1=0ull,aB0=0ull,aB1=0ull;
    #pragma unroll
    for (int q = 0; q < 16; ++q){
      ulonglong2 wv = w[q];
      aA0 = ffma2(wv.x, h2A[2*q],   aA0);
      aA1 = ffma2(wv.y, h2A[2*q+1], aA1);
      aB0 = ffma2(wv.x, h2B[2*q],   aB0);
      aB1 = ffma2(wv.y, h2B[2*q+1], aB1);
    }
    float bias = sm[OFF_B3];
    float2 ta0=upk2(aA0), ta1=upk2(aA1), tb0=upk2(aB0), tb1=upk2(aB1);
    sdfA = bias + ((ta0.x+ta1.x)+(ta0.y+ta1.y));
    sdfB = bias + ((tb0.x+tb1.x)+(tb0.y+tb1.y));
  }
  if (!skipA && !skipB){
    #pragma unroll 1
    for (int c = 1; c < 16; ++c){
      const ulonglong2* w = (const ulonglong2*)(cW3 + c*64);
      u64 aA0=0ull,aA1=0ull,aB0=0ull,aB1=0ull;
      #pragma unroll
      for (int q = 0; q < 16; ++q){
        ulonglong2 wv = w[q];
        aA0 = ffma2(wv.x, h2A[2*q],   aA0);
        aA1 = ffma2(wv.y, h2A[2*q+1], aA1);
        aB0 = ffma2(wv.x, h2B[2*q],   aB0);
        aB1 = ffma2(wv.y, h2B[2*q+1], aB1);
      }
      float bias = sm[OFF_B3+c];
      float2 ta0=upk2(aA0), ta1=upk2(aA1), tb0=upk2(aB0), tb1=upk2(aB1);
      featA[c-1] = bias + ((ta0.x+ta1.x)+(ta0.y+ta1.y));
      featB[c-1] = bias + ((tb0.x+tb1.x)+(tb0.y+tb1.y));
    }
  } else if (!skipA || !skipB){
    const u64* h2 = skipB ? h2A : h2B;
    float* feat   = skipB ? featA : featB;
    #pragma unroll 1
    for (int c = 1; c < 16; ++c){
      const ulonglong2* w = (const ulonglong2*)(cW3 + c*64);
      u64 a0=0ull, a1=0ull;
      #pragma unroll
      for (int q = 0; q < 16; ++q){
        ulonglong2 wv = w[q];
        a0 = ffma2(wv.x, h2[2*q],   a0);
        a1 = ffma2(wv.y, h2[2*q+1], a1);
      }
      float bias = sm[OFF_B3+c];
      float2 t0=upk2(a0), t1=upk2(a1);
      feat[c-1] = bias + ((t0.x+t1.x)+(t0.y+t1.y));
    }
  }

  // ---- backward: g2' = (0.01 W3[0][:]) * sigmoid(100 z2), overwrite h2 ----
  #pragma unroll
  for (int j = 0; j < 32; ++j){
    u64 w3p = ((const u64*)cW3)[j];
    float2 ta = upk2(h2A[j]);
    float2 tb = upk2(h2B[j]);
    h2A[j] = fmul2(w3p, pk2(dact1(ta.x), dact1(ta.y)));
    h2B[j] = fmul2(w3p, pk2(dact1(tb.x), dact1(tb.y)));
  }

  u64 deA[8], deB[8];
  #pragma unroll
  for (int i = 0; i < 8; ++i){ deA[i]=0ull; deB[i]=0ull; }

  #pragma unroll 2
  for (int k = 0; k < 64; ++k){
    const ulonglong2* w2p = (const ulonglong2*)(cW2T + k*64);
    u64 aA0=0ull,aA1=0ull,aB0=0ull,aB1=0ull;
    #pragma unroll
    for (int q = 0; q < 16; ++q){
      ulonglong2 wv = w2p[q];
      aA0 = ffma2(wv.x, h2A[2*q],   aA0);
      aA1 = ffma2(wv.y, h2A[2*q+1], aA1);
      aB0 = ffma2(wv.x, h2B[2*q],   aB0);
      aB1 = ffma2(wv.y, h2B[2*q+1], aB1);
    }
    float2 ta0=upk2(aA0), ta1=upk2(aA1), tb0=upk2(aB0), tb1=upk2(aB1);
    // packed dz: sums * stored sigmoid(100 z1)
    u64 dz = fmul2(pk2((ta0.x+ta1.x)+(ta0.y+ta1.y),
                       (tb0.x+tb1.x)+(tb0.y+tb1.y)),
                   s1p[k*TPB]);
    float2 d = upk2(dz);

    const ulonglong2* w1p = (const ulonglong2*)(sm + OFF_W1 + k*16);
    ulonglong2 wa=w1p[0], wb=w1p[1], wc=w1p[2], wd=w1p[3];
    const u64 dzAp = pk2(d.x,d.x), dzBp = pk2(d.y,d.y);
    deA[0]=ffma2(dzAp,wa.x,deA[0]); deA[1]=ffma2(dzAp,wa.y,deA[1]);
    deA[2]=ffma2(dzAp,wb.x,deA[2]); deA[3]=ffma2(dzAp,wb.y,deA[3]);
    deA[4]=ffma2(dzAp,wc.x,deA[4]); deA[5]=ffma2(dzAp,wc.y,deA[5]);
    deA[6]=ffma2(dzAp,wd.x,deA[6]); deA[7]=ffma2(dzAp,wd.y,deA[7]);
    deB[0]=ffma2(dzBp,wa.x,deB[0]); deB[1]=ffma2(dzBp,wa.y,deB[1]);
    deB[2]=ffma2(dzBp,wb.x,deB[2]); deB[3]=ffma2(dzBp,wb.y,deB[3]);
    deB[4]=ffma2(dzBp,wc.x,deB[4]); deB[5]=ffma2(dzBp,wc.y,deB[5]);
    deB[6]=ffma2(dzBp,wd.x,deB[6]); deB[7]=ffma2(dzBp,wd.y,deB[7]);
  }

  // ---- re-gather corners (packed dot) -> spatial gradient; normals ----
  // de is 1e-4-scaled (W2T and W3 both 0.01-prescaled) -> fold 1e4 into SCALE.
  float nxA,nyA,nzA, nxB,nyB,nzB;
  #pragma unroll
  for (int pi = 0; pi < PPT; ++pi){
    const Geo g = pi ? gB : gA;
    const u64* de = pi ? deB : deA;
    float gx=0.f, gy=0.f, gz=0.f;
    #pragma unroll
    for (int dx = 0; dx < 2; ++dx){
      const float wxv = dx ? g.fx : (1.0f - g.fx);
      #pragma unroll
      for (int dy = 0; dy < 2; ++dy){
        const float wyv = dy ? g.fy : (1.0f - g.fy);
        const ulonglong2* gp = (const ulonglong2*)(grid + g.base + dx*SX + dy*SY);
        u64 acc0=0ull, acc1=0ull;
        #pragma unroll
        for (int i = 0; i < 4; ++i){
          ulonglong2 a = gp[i];
          acc0 = ffma2(a.x, de[2*i],   acc0);
          acc0 = ffma2(a.y, de[2*i+1], acc0);
        }
        #pragma unroll
        for (int i = 0; i < 4; ++i){
          ulonglong2 b = gp[4+i];
          acc1 = ffma2(b.x, de[2*i],   acc1);
          acc1 = ffma2(b.y, de[2*i+1], acc1);
        }
        float2 t0 = upk2(acc0), t1 = upk2(acc1);
        float sA = t0.x + t0.y;
        float sB = t1.x + t1.y;
        float sc = fmaf(g.fz, sB - sA, sA);
        gz = fmaf(wxv*wyv, sB - sA, gz);
        gx += dx ? wyv*sc : -wyv*sc;
        gy += dy ? wxv*sc : -wxv*sc;
      }
    }
    const float SCALE = 0.5f*(float)(GG-1)/1.3f * 10000.0f;  // 1e4 compensates prescale
    const float Gx = g.ax ? gx*SCALE : 0.0f;
    const float Gy = g.ay ? gy*SCALE : 0.0f;
    const float Gz = g.az ? gz*SCALE : 0.0f;
    const int p = pi ? pB : pA;
    out_grads[3*p+0] = Gx;
    out_grads[3*p+1] = Gy;
    out_grads[3*p+2] = Gz;
    const float nn = sqrtf(Gx*Gx + Gy*Gy + Gz*Gz);
    const float inv = 1.0f / fmaxf(nn, 1e-12f);
    if (pi){ nxB=Gx*inv; nyB=Gy*inv; nzB=Gz*inv; }
    else   { nxA=Gx*inv; nyA=Gy*inv; nzA=Gz*inv; }
  }

  // ---- color MLP: skip fully-masked halves (their w is exactly 0 in compositing) ----
  float rgbA[3] = {0.f,0.f,0.f}, rgbB[3] = {0.f,0.f,0.f};

  if (!skipA && !skipB){
    u64 ciA[9], ciB[9];
    #pragma unroll
    for (int i = 0; i < 7; ++i){
      ciA[i] = pk2(featA[2*i], featA[2*i+1]);
      ciB[i] = pk2(featB[2*i], featB[2*i+1]);
    }
    ciA[7] = pk2(featA[14], nxA); ciA[8] = pk2(nyA, nzA);
    ciB[7] = pk2(featB[14], nxB); ciB[8] = pk2(nyB, nzB);

    #pragma unroll
    for (int j = 0; j < 32; ++j){
      u64 b = ((const u64*)(sm + OFF_CB2))[j];
      h2A[j]=b; h2B[j]=b;
    }

    #pragma unroll 1
    for (int j = 0; j < 64; ++j){
      const ulonglong2* w = (const ulonglong2*)(sm + OFF_CW1P + j*24);
      ulonglong2 wa=w[0], wb=w[1], wc=w[2], wd=w[3];
      u64 w8 = ((const u64*)(sm + OFF_CW1P + j*24))[8];
      const float bias = sm[OFF_CB1+j];
      u64 zA0=0ull, zA1=0ull, zB0=0ull, zB1=0ull;
      zA0=ffma2(wa.x,ciA[0],zA0); zA1=ffma2(wa.y,ciA[1],zA1);
      zA0=ffma2(wb.x,ciA[2],zA0); zA1=ffma2(wb.y,ciA[3],zA1);
      zA0=ffma2(wc.x,ciA[4],zA0); zA1=ffma2(wc.y,ciA[5],zA1);
      zA0=ffma2(wd.x,ciA[6],zA0); zA1=ffma2(wd.y,ciA[7],zA1);
      zA0=ffma2(w8,  ciA[8],zA0);
      zB0=ffma2(wa.x,ciB[0],zB0); zB1=ffma2(wa.y,ciB[1],zB1);
      zB0=ffma2(wb.x,ciB[2],zB0); zB1=ffma2(wb.y,ciB[3],zB1);
      zB0=ffma2(wc.x,ciB[4],zB0); zB1=ffma2(wc.y,ciB[5],zB1);
      zB0=ffma2(wd.x,ciB[6],zB0); zB1=ffma2(wd.y,ciB[7],zB1);
      zB0=ffma2(w8,  ciB[8],zB0);
      float2 ta0=upk2(zA0), ta1=upk2(zA1), tb0=upk2(zB0), tb1=upk2(zB1);
      float zA = bias + ((ta0.x+ta1.x)+(ta0.y+ta1.y));
      float zB = bias + ((tb0.x+tb1.x)+(tb0.y+tb1.y));
      float c1A = fmaxf(zA, 0.0f);
      float c1B = fmaxf(zB, 0.0f);
      const u64 cAp = pk2(c1A,c1A), cBp = pk2(c1B,c1B);
      const ulonglong2* wt = (const ulonglong2*)(cCW2T + j*64);
      #pragma unroll
      for (int q = 0; q < 16; ++q){
        ulonglong2 wv = wt[q];
        h2A[2*q]   = ffma2(wv.x, cAp, h2A[2*q]);
        h2A[2*q+1] = ffma2(wv.y, cAp, h2A[2*q+1]);
        h2B[2*q]   = ffma2(wv.x, cBp, h2B[2*q]);
        h2B[2*q+1] = ffma2(wv.y, cBp, h2B[2*q+1]);
      }
    }
    #pragma unroll
    for (int j = 0; j < 32; ++j){
      float2 ta = upk2(h2A[j]); h2A[j] = pk2(fmaxf(ta.x,0.0f), fmaxf(ta.y,0.0f));
      float2 tb = upk2(h2B[j]); h2B[j] = pk2(fmaxf(tb.x,0.0f), fmaxf(tb.y,0.0f));
    }

    #pragma unroll 1
    for (int c = 0; c < 3; ++c){
      const ulonglong2* w = (const ulonglong2*)(cCW3 + c*64);
      u64 aA0=0ull,aA1=0ull,aB0=0ull,aB1=0ull;
      #pragma unroll
      for (int q = 0; q < 16; ++q){
        ulonglong2 wv = w[q];
        aA0 = ffma2(wv.x, h2A[2*q],   aA0);
        aA1 = ffma2(wv.y, h2A[2*q+1], aA1);
        aB0 = ffma2(wv.x, h2B[2*q],   aB0);
        aB1 = ffma2(wv.y, h2B[2*q+1], aB1);
      }
      float bias = sm[OFF_CB3+c];
      float2 ta0=upk2(aA0), ta1=upk2(aA1), tb0=upk2(aB0), tb1=upk2(aB1);
      rgbA[c] = 1.0f / (1.0f + __expf(-(bias + ((ta0.x+ta1.x)+(ta0.y+ta1.y)))));
      rgbB[c] = 1.0f / (1.0f + __expf(-(bias + ((tb0.x+tb1.x)+(tb0.y+tb1.y)))));
    }
  } else if (!skipA || !skipB){
    // one half fully masked -> single-point color path for the live half
    u64 ci[9];
    const float* feat = skipB ? featA : featB;
    const float nx = skipB ? nxA : nxB;
    const float ny = skipB ? nyA : nyB;
    const float nz = skipB ? nzA : nzB;
    #pragma unroll
    for (int i = 0; i < 7; ++i) ci[i] = pk2(feat[2*i], feat[2*i+1]);
    ci[7] = pk2(feat[14], nx); ci[8] = pk2(ny, nz);
    float rgb[3];
    color_single(sm, ci, h2A, rgb);
    if (skipB){ rgbA[0]=rgb[0]; rgbA[1]=rgb[1]; rgbA[2]=rgb[2]; }
    else      { rgbB[0]=rgb[0]; rgbB[1]=rgb[1]; rgbB[2]=rgb[2]; }
  }
  // both skipped: rgb stays 0 (multiplied by exactly-zero weights downstream)

  // ---- sigma (Laplace CDF) + stores ----
  const float bet = 0.015f + fabsf(beta_p[0]);
  {
    const float s = sdfA;
    const float sgn = (s > 0.0f) ? 1.0f : ((s < 0.0f) ? -1.0f : 0.0f);
    float sigma = (0.5f + 0.5f*sgn*expm1f(-fabsf(s)/bet)) / bet;
    if (!inA) sigma = 0.0f;
    g_srgb[pA] = make_float4(sigma, rgbA[0], rgbA[1], rgbA[2]);
    g_nrm[pA]  = make_float4(nxA, nyA, nzA, 0.0f);
  }
  {
    const float s = sdfB;
    const float sgn = (s > 0.0f) ? 1.0f : ((s < 0.0f) ? -1.0f : 0.0f);
    float sigma = (0.5f + 0.5f*sgn*expm1f(-fabsf(s)/bet)) / bet;
    if (!inB) sigma = 0.0f;
    g_srgb[pB] = make_float4(sigma, rgbB[0], rgbB[1], rgbB[2]);
    g_nrm[pB]  = make_float4(nxB, nyB, nzB, 0.0f);
  }
}

// ---- per-ray compositing: one warp per ray, 2 samples per lane ----
__global__ void __launch_bounds__(256)
k_render(const float* __restrict__ rdn,
         const unsigned* __restrict__ near_p, const unsigned* __restrict__ far_p,
         float* __restrict__ out)
{
  const int gt = blockIdx.x*256 + threadIdx.x;
  const int r = gt >> 5;
  const int lane = gt & 31;
  if (r >= RR) return;

  const float nearf = decode_scalar(near_p);
  const float farf  = decode_scalar(far_p);
  const float span  = farf - nearf;
  const float dt    = span * (1.0f/64.0f);

  const int p0 = r*64 + lane, p1 = p0 + 32;
  float4 a0 = g_srgb[p0], a1 = g_srgb[p1];
  float4 n0 = g_nrm[p0],  n1 = g_nrm[p1];
  const float dd0 = a0.x * dt;
  const float dd1 = a1.x * dt;

  float cs0 = dd0;
  #pragma unroll
  for (int o = 1; o < 32; o <<= 1){ float v = __shfl_up_sync(0xffffffffu, cs0, o); if (lane >= o) cs0 += v; }
  const float tot0 = __shfl_sync(0xffffffffu, cs0, 31);
  float cs1 = dd1;
  #pragma unroll
  for (int o = 1; o < 32; o <<= 1){ float v = __shfl_up_sync(0xffffffffu, cs1, o); if (lane >= o) cs1 += v; }
  cs1 += tot0;

  const float T0 = __expf(dd0 - cs0);
  const float T1 = __expf(dd1 - cs1);
  const float w0 = (1.0f - __expf(-dd0)) * T0;
  const float w1 = (1.0f - __expf(-dd1)) * T1;
  const float tm0 = nearf + span * (((float)lane + 0.5f)  * (1.0f/64.0f));
  const float tm1 = nearf + span * (((float)lane + 32.5f) * (1.0f/64.0f));

  float v0 = w0*a0.y + w1*a1.y;
  float v1 = w0*a0.z + w1*a1.z;
  float v2 = w0*a0.w + w1*a1.w;
  float v3 = w0*tm0  + w1*tm1;
  float v4 = w0*n0.x + w1*n1.x;
  float v5 = w0*n0.y + w1*n1.y;
  float v6 = w0*n0.z + w1*n1.z;
  float v7 = w0 + w1;

  #pragma unroll
  for (int o = 16; o > 0; o >>= 1){
    v0 += __shfl_down_sync(0xffffffffu, v0, o);
    v1 += __shfl_down_sync(0xffffffffu, v1, o);
    v2 += __shfl_down_sync(0xffffffffu, v2, o);
    v3 += __shfl_down_sync(0xffffffffu, v3, o);
    v4 += __shfl_down_sync(0xffffffffu, v4, o);
    v5 += __shfl_down_sync(0xffffffffu, v5, o);
    v6 += __shfl_down_sync(0xffffffffu, v6, o);
    v7 += __shfl_down_sync(0xffffffffu, v7, o);
  }
  if (lane == 0){
    float* op = out + r*8;
    op[0]=v0; op[1]=v1; op[2]=v2;
    op[3]=v3 / rdn[r];
    op[4]=v4; op[5]=v5; op[6]=v6; op[7]=v7;
  }
}

extern "C" void kernel_launch(void* const* d_in, const int* in_sizes, int n_in,
                              void* d_out, int out_size)
{
  const float* rays_o = (const float*)d_in[0];
  const float* rays_d = (const float*)d_in[1];
  const float* rdn    = (const float*)d_in[2];
  const float* grid   = (const float*)d_in[3];
  const float* sw1 = (const float*)d_in[4];
  const float* sb1 = (const float*)d_in[5];
  const float* sw2 = (const float*)d_in[6];
  const float* sb2 = (const float*)d_in[7];
  const float* sw3 = (const float*)d_in[8];
  const float* sb3 = (const float*)d_in[9];
  const float* cw1 = (const float*)d_in[10];
  const float* cb1 = (const float*)d_in[11];
  const float* cw2 = (const float*)d_in[12];
  const float* cb2 = (const float*)d_in[13];
  const float* cw3 = (const float*)d_in[14];
  const float* cb3 = (const float*)d_in[15];
  const float* beta = (const float*)d_in[16];
  const unsigned* nearp = (const unsigned*)d_in[17];
  const unsigned* farp  = (const unsigned*)d_in[18];

  float* out = (float*)d_out;
  float* out_grads = out + RR*8;   // output = [rendered (R,8), sdf_grads (R*S,3)]

  // Resolve constant-bank addresses (pure address queries; no stream work).
  void *w2t_p = nullptr, *cw2t_p = nullptr, *w3_p = nullptr, *cw3_p = nullptr;
  cudaGetSymbolAddress(&w2t_p,  cW2T);
  cudaGetSymbolAddress(&cw2t_p, cCW2T);
  cudaGetSymbolAddress(&w3_p,   cW3);
  cudaGetSymbolAddress(&cw3_p,  cCW3);

  cudaFuncSetAttribute(k_points, cudaFuncAttributeMaxDynamicSharedMemorySize, SMEM_BYTES);

  // 1) prep kernel writes (prescaled) transposed weights into the constant bank
  k_prep<<<1, 256>>>(sw2, cw2, sw3, cw3,
                     (float*)w2t_p, (float*)cw2t_p, (float*)w3_p, (float*)cw3_p);

  // 2) main point kernel + compositing
  k_points<<<RR/4, TPB, SMEM_BYTES>>>(
      rays_o, rays_d, grid,
      sw1, sb1, sb2, sb3,
      cw1, cb1, cb2, cb3,
      beta, nearp, farp, out_grads);

  k_render<<<(RR*32)/256, 256>>>(rdn, nearp, farp, out);
}